// round 5
// baseline (speedup 1.0000x reference)
#include <cuda_runtime.h>
#include <cuda_bf16.h>
#include <cstdint>

#define HH      1024
#define NMODES  64
#define NPAIR   32          // mode pairs
#define LLEN    2048
#define TPB     128         // thread t owns l in [16t, 16t+16)
#define LPT     16          // l per thread

typedef unsigned long long u64;

// ---- packed f32x2 helpers (Blackwell packed fp32) ----
__device__ __forceinline__ u64 f2mul(u64 a, u64 b) {
    u64 d; asm("mul.rn.f32x2 %0,%1,%2;" : "=l"(d) : "l"(a), "l"(b)); return d;
}
__device__ __forceinline__ u64 f2fma(u64 a, u64 b, u64 c) {
    u64 d; asm("fma.rn.f32x2 %0,%1,%2,%3;" : "=l"(d) : "l"(a), "l"(b), "l"(c)); return d;
}
__device__ __forceinline__ u64 f2add(u64 a, u64 b) {
    u64 d; asm("add.rn.f32x2 %0,%1,%2;" : "=l"(d) : "l"(a), "l"(b)); return d;
}
__device__ __forceinline__ uint32_t smem_u32(const void* p) {
    uint32_t a;
    asm("{ .reg .u64 t; cvta.to.shared.u64 t, %1; cvt.u32.u64 %0, t; }" : "=r"(a) : "l"(p));
    return a;
}

__global__ __launch_bounds__(TPB, 7)   // 7 blocks/SM -> 148*7=1036 >= 1024: SINGLE WAVE
void ssd_vandermonde_v5_kernel(
    const float* __restrict__ log_dt,
    const float* __restrict__ log_w_real,
    const float* __restrict__ w_imag,
    const float* __restrict__ C_re,
    const float* __restrict__ C_im,
    float* __restrict__ out)
{
    // Per mode-pair k (modes 2k, 2k+1), packed lo/hi:
    //  Ptab[k][r]  = { Pr0, Pr1, Pi0, Pi1 }                   P  = z^(16r), r = 0..31 (lane)
    //  Qtab[k][q]  = { Qr, -Qi | Q'r, -Q'i } (8 floats)       Q  = 2*Cmod*z^(512q), Q' = Q*z, q = 0..3 (warp)
    //  PQtab[k]    = { 2zr0, 2zr1, -|z0|^2, -|z1|^2 }
    __shared__ float4 Ptab[NPAIR][32];      // 16 KB
    __shared__ float  Qtab[NPAIR][4][8];    //  4 KB
    __shared__ float4 PQtab[NPAIR];         // 512 B

    const int h   = blockIdx.x;
    const int tid = threadIdx.x;

    // ---------------- Setup: one thread per mode (64 threads) ----------------
    if (tid < NMODES) {
        const int n   = tid;
        const int k   = n >> 1;
        const int sub = n & 1;

        const float dt = expf(log_dt[h]);
        const float wr = -expf(log_w_real[h * NMODES + n]);
        const float wi = w_imag[h * NMODES + n];
        const float ar = wr * dt;
        const float ai = wi * dt;

        // z = exp(dtA)
        float s, c;
        const float ez = expf(ar);
        sincosf(ai, &s, &c);
        const float zr = ez * c;
        const float zi = ez * s;

        // 2*Cmod = 2*C*(z-1)/w
        const float den  = wr * wr + wi * wi;
        const float zm1r = zr - 1.0f;
        const float tr = (zm1r * wr + zi * wi) / den;
        const float ti = (zi * wr - zm1r * wi) / den;
        const float cr = C_re[h * NMODES + n];
        const float ci = C_im[h * NMODES + n];
        const float ur = 2.0f * (cr * tr - ci * ti);
        const float ui = 2.0f * (cr * ti + ci * tr);

        // z^16, z^512 via exp (scaled phase args are exact fp32 products)
        float s16, c16, s512, c512;
        const float e16 = expf(ar * 16.0f);
        sincosf(ai * 16.0f, &s16, &c16);
        const float z16r = e16 * c16, z16i = e16 * s16;
        const float e512 = expf(ar * 512.0f);
        sincosf(ai * 512.0f, &s512, &c512);
        const float z512r = e512 * c512, z512i = e512 * s512;

        // recurrence coefficients
        float* pq = reinterpret_cast<float*>(&PQtab[k]);
        pq[sub]     = zr + zr;
        pq[2 + sub] = -(zr * zr + zi * zi);

        // P table: z^(16r)
        float prc = 1.0f, pic = 0.0f;
        #pragma unroll 1
        for (int r = 0; r < 32; r++) {
            float* pt = reinterpret_cast<float*>(&Ptab[k][r]);
            pt[sub]     = prc;
            pt[2 + sub] = pic;
            const float nr = prc * z16r - pic * z16i;
            const float ni = prc * z16i + pic * z16r;
            prc = nr; pic = ni;
        }

        // Q table: Q = 2*Cmod*z^(512q), Q' = Q*z
        float qrc = ur, qic = ui;
        #pragma unroll 1
        for (int q = 0; q < 4; q++) {
            float* qt = &Qtab[k][q][0];
            const float qpr = qrc * zr - qic * zi;   // Q' = Q*z
            const float qpi = qrc * zi + qic * zr;
            qt[sub]     = qrc;
            qt[2 + sub] = -qic;
            qt[4 + sub] = qpr;
            qt[6 + sub] = -qpi;
            const float nr = qrc * z512r - qic * z512i;
            const float ni = qrc * z512i + qic * z512r;
            qrc = nr; qic = ni;
        }
    }
    __syncthreads();

    // ---------------- Main loop: thread owns l in [16*tid, 16*tid+16) ----------------
    const int r  = tid & 31;   // lane -> P index
    const int qi = tid >> 5;   // warp -> Q index (uniform within warp)

    const uint32_t aP  = smem_u32(&Ptab[0][r]);
    const uint32_t aQ  = smem_u32(&Qtab[0][qi][0]);
    const uint32_t aPQ = smem_u32(&PQtab[0]);

    u64 acc[LPT];
    #pragma unroll
    for (int d = 0; d < LPT; d++) acc[d] = 0ull;

    #pragma unroll 2
    for (int k = 0; k < NPAIR; k++) {
        u64 pr2, pi2, qr2, qni2, qpr2, qpni2, pp2, qn2;
        asm("ld.shared.v2.u64 {%0,%1},[%2];" : "=l"(pr2),  "=l"(pi2)   : "r"(aP  + k * 512));
        asm("ld.shared.v2.u64 {%0,%1},[%2];" : "=l"(qr2),  "=l"(qni2)  : "r"(aQ  + k * 128));
        asm("ld.shared.v2.u64 {%0,%1},[%2];" : "=l"(qpr2), "=l"(qpni2) : "r"(aQ  + k * 128 + 16));
        asm("ld.shared.v2.u64 {%0,%1},[%2];" : "=l"(pp2),  "=l"(qn2)   : "r"(aPQ + k * 16));

        // x0 = Re(Q*P), x1 = Re(Q'*P)   (Q' = Q*z precomputed)
        u64 xa = f2fma(qni2,  pi2, f2mul(qr2,  pr2));
        u64 xb = f2fma(qpni2, pi2, f2mul(qpr2, pr2));

        acc[0] = f2add(acc[0], xa);
        acc[1] = f2add(acc[1], xb);

        // x_d = 2Re(z)*x_{d-1} - |z|^2*x_{d-2}
        #pragma unroll
        for (int d = 2; d < LPT; d++) {
            const u64 xn = f2fma(pp2, xb, f2mul(qn2, xa));
            acc[d] = f2add(acc[d], xn);
            xa = xb; xb = xn;
        }
    }

    // ---------------- Epilogue: fold packed halves, coalesced store ----------------
    float res[LPT];
    #pragma unroll
    for (int d = 0; d < LPT; d++) {
        float lo, hi;
        asm("mov.b64 {%0,%1},%2;" : "=f"(lo), "=f"(hi) : "l"(acc[d]));
        res[d] = lo + hi;
    }

    float4* o = reinterpret_cast<float4*>(out + (size_t)h * LLEN + tid * LPT);
    #pragma unroll
    for (int v = 0; v < LPT / 4; v++) {
        o[v] = make_float4(res[4 * v], res[4 * v + 1], res[4 * v + 2], res[4 * v + 3]);
    }
}

extern "C" void kernel_launch(void* const* d_in, const int* in_sizes, int n_in,
                              void* d_out, int out_size)
{
    const float* log_dt     = (const float*)d_in[0];
    const float* log_w_real = (const float*)d_in[1];
    const float* w_imag     = (const float*)d_in[2];
    const float* C_re       = (const float*)d_in[3];
    const float* C_im       = (const float*)d_in[4];
    float*       out        = (float*)d_out;

    ssd_vandermonde_v5_kernel<<<HH, TPB>>>(log_dt, log_w_real, w_imag, C_re, C_im, out);
}

// round 6
// speedup vs baseline: 1.9723x; 1.9723x over previous
#include <cuda_runtime.h>
#include <cuda_bf16.h>
#include <cstdint>

#define HH      1024
#define NMODES  64
#define LLEN    2048
#define TPB     128
#define GRID    512          // 2 heads per CTA

// smem layout (dynamic):
//  Asm: 32 x 132 u32 (tf32 bits)   A'[a][k], k<64: Re(c*z64^a), k>=64: Im
//  Bsm: 128 x 68 u32 (tf32 bits)   B'[k][b], k<64: Re(z^b),     k>=64: -Im(z^b)
//  SC : 64 x 12 f32 per-mode consts {zr,zi,z32r,z32i,z64r,z64i,z1024r,z1024i,cr,ci}
#define A_STRIDE 132
#define B_STRIDE 68
#define SC_STRIDE 12
#define A_WORDS  (32 * A_STRIDE)
#define B_WORDS  (128 * B_STRIDE)
#define SC_WORDS (64 * SC_STRIDE)
#define SMEM_BYTES ((A_WORDS + B_WORDS + SC_WORDS) * 4)

__device__ __forceinline__ uint32_t tf32c(float f) {
    uint32_t r; asm("cvt.rna.tf32.f32 %0,%1;" : "=r"(r) : "f"(f)); return r;
}

__device__ __forceinline__ void mma8(float* d,
                                     uint32_t a0, uint32_t a1, uint32_t a2, uint32_t a3,
                                     uint32_t b0, uint32_t b1) {
    asm volatile(
        "mma.sync.aligned.m16n8k8.row.col.f32.tf32.tf32.f32 "
        "{%0,%1,%2,%3},{%4,%5,%6,%7},{%8,%9},{%0,%1,%2,%3};"
        : "+f"(d[0]), "+f"(d[1]), "+f"(d[2]), "+f"(d[3])
        : "r"(a0), "r"(a1), "r"(a2), "r"(a3), "r"(b0), "r"(b1));
}

__global__ __launch_bounds__(TPB, 4)
void ssd_tc_kernel(
    const float* __restrict__ log_dt,
    const float* __restrict__ log_w_real,
    const float* __restrict__ w_imag,
    const float* __restrict__ C_re,
    const float* __restrict__ C_im,
    float* __restrict__ out)
{
    extern __shared__ char smem_raw[];
    uint32_t* Asm = reinterpret_cast<uint32_t*>(smem_raw);
    uint32_t* Bsm = Asm + A_WORDS;
    float*    SC  = reinterpret_cast<float*>(Bsm + B_WORDS);

    const int tid  = threadIdx.x;
    const int lane = tid & 31;
    const int warp = tid >> 5;
    const int n    = tid & 63;     // mode
    const int half = tid >> 6;     // 0/1
    const int r4   = lane >> 2;    // 0..7
    const int c4   = lane & 3;     // 0..3

    for (int rep = 0; rep < 2; rep++) {
        const int h = blockIdx.x * 2 + rep;

        // ---------- Phase 1: per-mode constants (64 threads) ----------
        if (tid < NMODES) {
            const float dt = expf(log_dt[h]);
            const float wr = -expf(log_w_real[h * NMODES + n]);
            const float wi = w_imag[h * NMODES + n];
            const float ar = wr * dt;
            const float ai = wi * dt;

            float s, c;
            const float ez = expf(ar);
            sincosf(ai, &s, &c);
            const float zr = ez * c, zi = ez * s;

            // 2*Cmod = 2*C*(z-1)/w
            const float den = wr * wr + wi * wi;
            const float zm  = zr - 1.0f;
            const float tr  = (zm * wr + zi * wi) / den;
            const float ti  = (zi * wr - zm * wi) / den;
            const float cre = C_re[h * NMODES + n];
            const float cim = C_im[h * NMODES + n];
            const float qr  = 2.0f * (cre * tr - cim * ti);
            const float qi  = 2.0f * (cre * ti + cim * tr);

            // z^32, z^64, z^1024 (power-of-two phase scalings are exact fp32)
            float s32, c32, s64, c64, s1k, c1k;
            const float e32 = expf(ar * 32.0f);   sincosf(ai * 32.0f,   &s32, &c32);
            const float e64 = expf(ar * 64.0f);   sincosf(ai * 64.0f,   &s64, &c64);
            const float e1k = expf(ar * 1024.0f); sincosf(ai * 1024.0f, &s1k, &c1k);

            float* sc = SC + n * SC_STRIDE;
            sc[0] = zr;          sc[1] = zi;
            sc[2] = e32 * c32;   sc[3] = e32 * s32;
            sc[4] = e64 * c64;   sc[5] = e64 * s64;
            sc[6] = e1k * c1k;   sc[7] = e1k * s1k;
            sc[8] = qr;          sc[9] = qi;
        }
        __syncthreads();

        // ---------- Phase 2: A' generation (A[a][n] = c*z64^a) ----------
        {
            const float* sc = SC + n * SC_STRIDE;
            const float z64r = sc[4], z64i = sc[5];
            float ur = sc[8], ui = sc[9];
            if (half) {  // start at c*z64^16 = c*z^1024
                const float pr = sc[6], pi = sc[7];
                const float t = ur * pr - ui * pi;
                ui = ur * pi + ui * pr; ur = t;
            }
            uint32_t* arow = Asm + (half * 16) * A_STRIDE;
            #pragma unroll
            for (int a = 0; a < 16; a++) {
                arow[n]          = tf32c(ur);
                arow[64 + n]     = tf32c(ui);
                const float t = ur * z64r - ui * z64i;
                ui = ur * z64i + ui * z64r; ur = t;
                arow += A_STRIDE;
            }
        }

        // ---------- Phase 3: B' generation (B[n][b] = z^b) ----------
        {
            const float* sc = SC + n * SC_STRIDE;
            const float zr = sc[0], zi = sc[1];
            float vr = 1.0f, vi = 0.0f;
            if (half) { vr = sc[2]; vi = sc[3]; }   // start at z^32
            uint32_t* b0 = Bsm + n * B_STRIDE + half * 32;
            uint32_t* b1 = Bsm + (64 + n) * B_STRIDE + half * 32;
            #pragma unroll
            for (int j = 0; j < 32; j++) {
                b0[j] = tf32c(vr);
                b1[j] = tf32c(-vi);
                const float t = vr * zr - vi * zi;
                vi = vr * zi + vi * zr; vr = t;
            }
        }
        __syncthreads();

        // ---------- Phase 4: GEMM 32x64x128 (tf32 mma.sync), warp owns 16 N-cols ----------
        float acc[16];
        #pragma unroll
        for (int i = 0; i < 16; i++) acc[i] = 0.0f;

        const uint32_t* A0 = Asm + r4 * A_STRIDE + c4;
        const uint32_t* B0 = Bsm + c4 * B_STRIDE + 16 * warp + r4;

        #pragma unroll
        for (int kk = 0; kk < 16; kk++) {
            const uint32_t* Ak = A0 + kk * 8;
            const uint32_t a00 = Ak[0];
            const uint32_t a01 = Ak[8 * A_STRIDE];
            const uint32_t a02 = Ak[4];
            const uint32_t a03 = Ak[8 * A_STRIDE + 4];
            const uint32_t* Ak1 = Ak + 16 * A_STRIDE;
            const uint32_t a10 = Ak1[0];
            const uint32_t a11 = Ak1[8 * A_STRIDE];
            const uint32_t a12 = Ak1[4];
            const uint32_t a13 = Ak1[8 * A_STRIDE + 4];

            const uint32_t* Bk = B0 + kk * 8 * B_STRIDE;
            const uint32_t b00 = Bk[0];
            const uint32_t b01 = Bk[4 * B_STRIDE];
            const uint32_t b10 = Bk[8];
            const uint32_t b11 = Bk[4 * B_STRIDE + 8];

            mma8(acc + 0,  a00, a01, a02, a03, b00, b01);   // mt0, nt0
            mma8(acc + 4,  a00, a01, a02, a03, b10, b11);   // mt0, nt1
            mma8(acc + 8,  a10, a11, a12, a13, b00, b01);   // mt1, nt0
            mma8(acc + 12, a10, a11, a12, a13, b10, b11);   // mt1, nt1
        }

        // ---------- Phase 5: store (l = 64*a + b) ----------
        float* op = out + (size_t)h * LLEN;
        #pragma unroll
        for (int mt = 0; mt < 2; mt++) {
            #pragma unroll
            for (int nt = 0; nt < 2; nt++) {
                const float* a = acc + (mt * 2 + nt) * 4;
                const int row = 16 * mt + r4;
                const int col = 16 * warp + 8 * nt + 2 * c4;
                *reinterpret_cast<float2*>(op + row * 64 + col)       = make_float2(a[0], a[1]);
                *reinterpret_cast<float2*>(op + (row + 8) * 64 + col) = make_float2(a[2], a[3]);
            }
        }
        __syncthreads();   // protect smem reuse by next rep
    }
}

extern "C" void kernel_launch(void* const* d_in, const int* in_sizes, int n_in,
                              void* d_out, int out_size)
{
    const float* log_dt     = (const float*)d_in[0];
    const float* log_w_real = (const float*)d_in[1];
    const float* w_imag     = (const float*)d_in[2];
    const float* C_re       = (const float*)d_in[3];
    const float* C_im       = (const float*)d_in[4];
    float*       out        = (float*)d_out;

    cudaFuncSetAttribute(ssd_tc_kernel,
                         cudaFuncAttributeMaxDynamicSharedMemorySize, SMEM_BYTES);
    ssd_tc_kernel<<<GRID, TPB, SMEM_BYTES>>>(log_dt, log_w_real, w_imag, C_re, C_im, out);
}

// round 7
// speedup vs baseline: 2.0556x; 1.0422x over previous
#include <cuda_runtime.h>
#include <cuda_bf16.h>
#include <cstdint>

#define HH      1024
#define NMODES  64
#define LLEN    2048
#define TPB     128
#define GRID    512          // 2 heads per CTA, sequential

// smem layout (dynamic):
//  Asm: 32 x 132 u32   A'[a][k], k=2n: Re(c*z64^a), k=2n+1: Im(c*z64^a)
//  Bt : 64 x 132 u32   Bt[b][k], k=2n: Re(z^b),     k=2n+1: -Im(z^b)
//  SC : 64 x 13 f32    per-mode consts
#define A_STRIDE 132
#define B_STRIDE 132
#define SC_STRIDE 13
#define A_WORDS  (32 * A_STRIDE)
#define B_WORDS  (64 * B_STRIDE)
#define SC_WORDS (64 * SC_STRIDE)
#define SMEM_BYTES ((A_WORDS + B_WORDS + SC_WORDS) * 4)

__device__ __forceinline__ uint32_t tf32c(float f) {
    uint32_t r; asm("cvt.rna.tf32.f32 %0,%1;" : "=r"(r) : "f"(f)); return r;
}

__device__ __forceinline__ void sts_v2(uint32_t addr, uint32_t a, uint32_t b) {
    asm volatile("st.shared.v2.u32 [%0],{%1,%2};" :: "r"(addr), "r"(a), "r"(b) : "memory");
}

__device__ __forceinline__ uint32_t smem_u32(const void* p) {
    uint32_t a;
    asm("{ .reg .u64 t; cvta.to.shared.u64 t, %1; cvt.u32.u64 %0, t; }" : "=r"(a) : "l"(p));
    return a;
}

__device__ __forceinline__ void mma8(float* d,
                                     uint32_t a0, uint32_t a1, uint32_t a2, uint32_t a3,
                                     uint32_t b0, uint32_t b1) {
    asm volatile(
        "mma.sync.aligned.m16n8k8.row.col.f32.tf32.tf32.f32 "
        "{%0,%1,%2,%3},{%4,%5,%6,%7},{%8,%9},{%0,%1,%2,%3};"
        : "+f"(d[0]), "+f"(d[1]), "+f"(d[2]), "+f"(d[3])
        : "r"(a0), "r"(a1), "r"(a2), "r"(a3), "r"(b0), "r"(b1));
}

__global__ __launch_bounds__(TPB, 4)
void ssd_tc_v7_kernel(
    const float* __restrict__ log_dt,
    const float* __restrict__ log_w_real,
    const float* __restrict__ w_imag,
    const float* __restrict__ C_re,
    const float* __restrict__ C_im,
    float* __restrict__ out)
{
    extern __shared__ char smem_raw[];
    uint32_t* Asm = reinterpret_cast<uint32_t*>(smem_raw);
    uint32_t* Bt  = Asm + A_WORDS;
    float*    SC  = reinterpret_cast<float*>(Bt + B_WORDS);

    const int tid  = threadIdx.x;
    const int lane = tid & 31;
    const int warp = tid >> 5;
    const int n    = tid & 63;     // mode
    const int half = tid >> 6;     // 0/1
    const int r4   = lane >> 2;    // 0..7
    const int c4   = lane & 3;     // 0..3

    const uint32_t aA  = smem_u32(Asm);
    const uint32_t aB  = smem_u32(Bt);

    for (int rep = 0; rep < 2; rep++) {
        const int h = blockIdx.x * 2 + rep;

        // ---------- Phase 1: per-mode constants (64 threads) ----------
        if (tid < NMODES) {
            const float dt = expf(log_dt[h]);
            const float wr = -expf(log_w_real[h * NMODES + n]);
            const float wi = w_imag[h * NMODES + n];
            const float ar = wr * dt;
            const float ai = wi * dt;

            float s, c;
            const float ez = expf(ar);
            sincosf(ai, &s, &c);
            const float zr = ez * c, zi = ez * s;

            // 2*Cmod = 2*C*(z-1)/w
            const float den = wr * wr + wi * wi;
            const float zm  = zr - 1.0f;
            const float tr  = (zm * wr + zi * wi) / den;
            const float ti  = (zi * wr - zm * wi) / den;
            const float cre = C_re[h * NMODES + n];
            const float cim = C_im[h * NMODES + n];
            const float qr  = 2.0f * (cre * tr - cim * ti);
            const float qi  = 2.0f * (cre * ti + cim * tr);

            // z^32, z^64, z^1024 (power-of-two phase scalings are exact fp32)
            float s32, c32, s64, c64, s1k, c1k;
            const float e32 = expf(ar * 32.0f);   sincosf(ai * 32.0f,   &s32, &c32);
            const float e64 = expf(ar * 64.0f);   sincosf(ai * 64.0f,   &s64, &c64);
            const float e1k = expf(ar * 1024.0f); sincosf(ai * 1024.0f, &s1k, &c1k);

            float* sc = SC + n * SC_STRIDE;
            sc[0] = zr;          sc[1] = zi;
            sc[2] = e32 * c32;   sc[3] = e32 * s32;
            sc[4] = e64 * c64;   sc[5] = e64 * s64;
            sc[6] = e1k * c1k;   sc[7] = e1k * s1k;
            sc[8] = qr;          sc[9] = qi;
        }
        __syncthreads();

        // ---------- Phase 2: A' generation (A[a][2n,2n+1] = c*z64^a) ----------
        {
            const float* sc = SC + n * SC_STRIDE;
            const float z64r = sc[4], z64i = sc[5];
            float ur = sc[8], ui = sc[9];
            if (half) {  // start at c*z64^16 = c*z^1024
                const float pr = sc[6], pi = sc[7];
                const float t = ur * pr - ui * pi;
                ui = ur * pi + ui * pr; ur = t;
            }
            uint32_t addr = aA + ((half * 16) * A_STRIDE + 2 * n) * 4;
            #pragma unroll
            for (int a = 0; a < 16; a++) {
                sts_v2(addr, tf32c(ur), tf32c(ui));
                const float t = ur * z64r - ui * z64i;
                ui = ur * z64i + ui * z64r; ur = t;
                addr += A_STRIDE * 4;
            }
        }

        // ---------- Phase 3: B generation (Bt[b][2n]=Re(z^b), [2n+1]=-Im) ----------
        {
            const float* sc = SC + n * SC_STRIDE;
            const float zr = sc[0], zi = sc[1];
            float vr = 1.0f, vi = 0.0f;
            if (half) { vr = sc[2]; vi = sc[3]; }   // start at z^32
            uint32_t addr = aB + ((half * 32) * B_STRIDE + 2 * n) * 4;
            #pragma unroll
            for (int j = 0; j < 32; j++) {
                sts_v2(addr, tf32c(vr), tf32c(-vi));
                const float t = vr * zr - vi * zi;
                vi = vr * zi + vi * zr; vr = t;
                addr += B_STRIDE * 4;
            }
        }
        __syncthreads();

        // ---------- Phase 4: GEMM 32x64x128 (tf32 mma.sync), warp owns 16 b-cols ----------
        float acc[16];
        #pragma unroll
        for (int i = 0; i < 16; i++) acc[i] = 0.0f;

        const uint32_t* A0 = Asm + r4 * A_STRIDE + c4;
        const uint32_t* B0 = Bt + (16 * warp + r4) * B_STRIDE + c4;

        #pragma unroll
        for (int kk = 0; kk < 16; kk++) {
            const uint32_t* Ak = A0 + kk * 8;
            const uint32_t a00 = Ak[0];
            const uint32_t a01 = Ak[8 * A_STRIDE];
            const uint32_t a02 = Ak[4];
            const uint32_t a03 = Ak[8 * A_STRIDE + 4];
            const uint32_t* Ak1 = Ak + 16 * A_STRIDE;
            const uint32_t a10 = Ak1[0];
            const uint32_t a11 = Ak1[8 * A_STRIDE];
            const uint32_t a12 = Ak1[4];
            const uint32_t a13 = Ak1[8 * A_STRIDE + 4];

            const uint32_t* Bk = B0 + kk * 8;
            const uint32_t b00 = Bk[0];
            const uint32_t b01 = Bk[4];
            const uint32_t b10 = Bk[8 * B_STRIDE];
            const uint32_t b11 = Bk[8 * B_STRIDE + 4];

            mma8(acc + 0,  a00, a01, a02, a03, b00, b01);   // mt0, nt0
            mma8(acc + 4,  a00, a01, a02, a03, b10, b11);   // mt0, nt1
            mma8(acc + 8,  a10, a11, a12, a13, b00, b01);   // mt1, nt0
            mma8(acc + 12, a10, a11, a12, a13, b10, b11);   // mt1, nt1
        }

        // ---------- Phase 5: store (l = 64*a + b) ----------
        float* op = out + (size_t)h * LLEN;
        #pragma unroll
        for (int mt = 0; mt < 2; mt++) {
            #pragma unroll
            for (int nt = 0; nt < 2; nt++) {
                const float* a = acc + (mt * 2 + nt) * 4;
                const int row = 16 * mt + r4;
                const int col = 16 * warp + 8 * nt + 2 * c4;
                *reinterpret_cast<float2*>(op + row * 64 + col)       = make_float2(a[0], a[1]);
                *reinterpret_cast<float2*>(op + (row + 8) * 64 + col) = make_float2(a[2], a[3]);
            }
        }
        __syncthreads();   // protect smem reuse by next rep
    }
}

extern "C" void kernel_launch(void* const* d_in, const int* in_sizes, int n_in,
                              void* d_out, int out_size)
{
    const float* log_dt     = (const float*)d_in[0];
    const float* log_w_real = (const float*)d_in[1];
    const float* w_imag     = (const float*)d_in[2];
    const float* C_re       = (const float*)d_in[3];
    const float* C_im       = (const float*)d_in[4];
    float*       out        = (float*)d_out;

    cudaFuncSetAttribute(ssd_tc_v7_kernel,
                         cudaFuncAttributeMaxDynamicSharedMemorySize, SMEM_BYTES);
    ssd_tc_v7_kernel<<<GRID, TPB, SMEM_BYTES>>>(log_dt, log_w_real, w_imag, C_re, C_im, out);
}